// round 13
// baseline (speedup 1.0000x reference)
#include <cuda_runtime.h>
#include <cuda_fp16.h>
#include <cstdint>

#define H  16
#define S  4096
#define DH 128
#define DM 2048
#define BM 128
#define BN 64
#define NT 256            // 8 warps, each owns 16 Q rows x full KV width
#define NQT 32            // S/BM Q-tiles per head

// byte offsets in dynamic SMEM; strides mod 128 == 16 -> conflict-free LDSM
#define QSTR  272         // Q row: 256B data + 16 pad
#define KSTR  272
#define VSTR  144         // V row: 128B data + 16 pad
#define B_Q   0
#define QSZ   (128*QSTR)  // 34816
#define KSZ   (64*KSTR)   // 17408
#define VSZ   (128*VSTR)  // 18432
#define B_K0  QSZ
#define B_K1  (B_K0 + KSZ)
#define B_V0  (B_K1 + KSZ)
#define B_V1  (B_V0 + VSZ)
#define SMEM_BYTES (B_V1 + VSZ)   // 106496 -> 2 CTAs/SM

// Prepass scratch: fp16, NATURAL row-major (ldmatrix does the fragment mapping).
// g_Qh/g_Kh: [head][row][d=128] (Q pre-scaled). g_Vh: [head][kvTile=64][d=128][kv=64]
__device__ __align__(16) __half g_Qh[H*S*DH];
__device__ __align__(16) __half g_Kh[H*S*DH];
__device__ __align__(16) __half g_Vh[H*S*DH];

__device__ __forceinline__ float ex2f(float x){
    float r; asm("ex2.approx.ftz.f32 %0, %1;" : "=f"(r) : "f"(x)); return r;
}
__device__ __forceinline__ uint32_t packh2(float lo, float hi){
    uint32_t d; asm("cvt.rn.f16x2.f32 %0, %1, %2;" : "=r"(d) : "f"(hi), "f"(lo));
    return d;
}
__device__ __forceinline__ uint4 ldsm4(uint32_t a){
    uint4 r;
    asm volatile("ldmatrix.sync.aligned.m8n8.x4.shared.b16 {%0,%1,%2,%3}, [%4];"
        : "=r"(r.x), "=r"(r.y), "=r"(r.z), "=r"(r.w) : "r"(a));
    return r;
}
__device__ __forceinline__ void mma16816(float c[4],
    uint32_t a0, uint32_t a1, uint32_t a2, uint32_t a3, uint32_t b0, uint32_t b1)
{
    asm volatile(
        "mma.sync.aligned.m16n8k16.row.col.f32.f16.f16.f32 "
        "{%0,%1,%2,%3}, {%4,%5,%6,%7}, {%8,%9}, {%0,%1,%2,%3};\n"
        : "+f"(c[0]), "+f"(c[1]), "+f"(c[2]), "+f"(c[3])
        : "r"(a0), "r"(a1), "r"(a2), "r"(a3), "r"(b0), "r"(b1));
}
__device__ __forceinline__ void cpa16(uint32_t dst, const void* src){
    asm volatile("cp.async.cg.shared.global [%0], [%1], 16;" :: "r"(dst), "l"(src));
}
__device__ __forceinline__ void cpa_commit(){
    asm volatile("cp.async.commit_group;" ::: "memory");
}
__device__ __forceinline__ void cpa_wait0(){
    asm volatile("cp.async.wait_group 0;" ::: "memory");
}

// ---- Fused prepass: blocks [0,2048) convert Q,K; blocks [2048,4096) convert V ----
__global__ void prep_all(const float* __restrict__ Q, const float* __restrict__ K,
                         const float* __restrict__ V)
{
    if (blockIdx.x < 2048){
        const float SC = 0.088388347648318447f * 1.4426950408889634f; // 1/sqrt(128)*log2e
        size_t base = ((size_t)blockIdx.x * 256 + threadIdx.x) * 16;
        {
            const float4* q = (const float4*)(Q + base);
            float4 x0=q[0], x1=q[1], x2=q[2], x3=q[3];
            __half2 h[8];
            h[0]=__floats2half2_rn(x0.x*SC,x0.y*SC); h[1]=__floats2half2_rn(x0.z*SC,x0.w*SC);
            h[2]=__floats2half2_rn(x1.x*SC,x1.y*SC); h[3]=__floats2half2_rn(x1.z*SC,x1.w*SC);
            h[4]=__floats2half2_rn(x2.x*SC,x2.y*SC); h[5]=__floats2half2_rn(x2.z*SC,x2.w*SC);
            h[6]=__floats2half2_rn(x3.x*SC,x3.y*SC); h[7]=__floats2half2_rn(x3.z*SC,x3.w*SC);
            *(float4*)(g_Qh+base)   = *(float4*)(h);
            *(float4*)(g_Qh+base+8) = *(float4*)(h+4);
        }
        {
            const float4* k = (const float4*)(K + base);
            float4 x0=k[0], x1=k[1], x2=k[2], x3=k[3];
            __half2 h[8];
            h[0]=__floats2half2_rn(x0.x,x0.y); h[1]=__floats2half2_rn(x0.z,x0.w);
            h[2]=__floats2half2_rn(x1.x,x1.y); h[3]=__floats2half2_rn(x1.z,x1.w);
            h[4]=__floats2half2_rn(x2.x,x2.y); h[5]=__floats2half2_rn(x2.z,x2.w);
            h[6]=__floats2half2_rn(x3.x,x3.y); h[7]=__floats2half2_rn(x3.z,x3.w);
            *(float4*)(g_Kh+base)   = *(float4*)(h);
            *(float4*)(g_Kh+base+8) = *(float4*)(h+4);
        }
    } else {
        int b2   = blockIdx.x - 2048;           // [0,2048)
        int head = b2 >> 7;
        int T    = (b2 >> 1) & 63;
        int kb   = (b2 & 1) * 2 + (threadIdx.x >> 7);
        int d    = threadIdx.x & 127;
        int kv0  = T * 64 + kb * 16;
        const float* src = V + ((size_t)head * S + kv0) * DH + d;
        float x[16];
        #pragma unroll
        for (int w = 0; w < 16; ++w) x[w] = src[(size_t)w * DH];
        __half2 h[8];
        #pragma unroll
        for (int i = 0; i < 8; ++i) h[i] = __floats2half2_rn(x[2*i], x[2*i+1]);
        __half* dst = g_Vh + (((size_t)head*64 + T)*128 + d)*64 + kb*16;
        *(float4*)(dst)   = *(float4*)(h);
        *(float4*)(dst+8) = *(float4*)(h+4);
    }
}

// ---------------- Main flash-attention kernel ----------------
// 296-CTA static schedule (2 CTAs/SM exactly; per-CTA cost in [28,32] units):
//   bid <  80 : single tile  head=bid&15,  qt=31-(bid>>4)
//   bid >= 80 : p2=bid-80
//     p2 < 208: same-head pair  head=p2&15, tiles qt=26-(p2>>4), qt=(p2>>4)
//     else    : cross-head pair i=p2-208: (head=2i,qt=13),(head=2i+1,qt=13)
extern __shared__ char smc[];

__global__ __launch_bounds__(NT, 2)
void fa_kernel(float* __restrict__ Out)
{
    const int bid = (int)blockIdx.x;
    int h0, q0t, h1, q1t, nseg;
    if (bid < 80){
        h0 = bid & 15;  q0t = 31 - (bid >> 4);
        h1 = 0; q1t = 0; nseg = 1;
    } else {
        int p2 = bid - 80;
        if (p2 < 208){
            int c = p2 >> 4;
            h0 = h1 = p2 & 15;
            q0t = 26 - c;  q1t = c;
        } else {
            int i = p2 - 208;
            h0 = 2*i;  h1 = 2*i + 1;
            q0t = q1t = 13;
        }
        nseg = 2;
    }

    const int tid  = threadIdx.x;
    const int lane = tid & 31;
    const int warp = tid >> 5;
    const int gid  = lane >> 2;
    const int t4   = lane & 3;
    const int mbase = warp * 16;       // this warp's 16 rows

    const uint32_t smb = (uint32_t)__cvta_generic_to_shared(smc);
    const float NEGINF = __int_as_float(0xff800000);

    // per-lane ldmatrix row-address components (loop-invariant)
    const uint32_t qln  = smb + B_Q + (uint32_t)(mbase + (lane & 15))*QSTR + (lane >> 4)*16;
    const uint32_t kOff = (uint32_t)(lane & 7)*KSTR + (lane >> 3)*16;
    const uint32_t vOff = (uint32_t)(lane & 7)*VSTR + (lane >> 3)*16;

    #pragma unroll 1
    for (int seg = 0; seg < nseg; ++seg){
        const int head = seg ? h1 : h0;
        const int qt   = seg ? q1t : q0t;
        const int q0   = qt * BM;
        const int jmax = 2*qt + 2;
        const char* gQ = (const char*)(g_Qh + ((size_t)head*S + q0) * DH);
        const char* gK = (const char*)(g_Kh + (size_t)head*S*DH);
        const char* gV = (const char*)(g_Vh + (size_t)head*S*DH);

        __syncthreads();   // prior segment fully done with all SMEM buffers

        // ---- Prologue: Q tile + K/V tile 0 ----
        #pragma unroll
        for (int it = 0; it < 8; ++it){
            int i = it*NT + tid; int r = i >> 4, c = (i & 15) * 16;
            cpa16(smb + B_Q + r*QSTR + c, gQ + r*256 + c);
        }
        #pragma unroll
        for (int it = 0; it < 4; ++it){
            int i = it*NT + tid; int r = i >> 4, c = (i & 15) * 16;
            cpa16(smb + B_K0 + r*KSTR + c, gK + r*256 + c);
        }
        #pragma unroll
        for (int it = 0; it < 4; ++it){
            int i = it*NT + tid; int r = i >> 3, c = (i & 7) * 16;
            cpa16(smb + B_V0 + r*VSTR + c, gV + r*128 + c);
        }
        cpa_commit();

        float o[16][4];
        #pragma unroll
        for (int nt = 0; nt < 16; ++nt)
            o[nt][0] = o[nt][1] = o[nt][2] = o[nt][3] = 0.f;
        float m0 = NEGINF, m1 = NEGINF, l0 = 0.f, l1 = 0.f;

        #pragma unroll 1
        for (int j = 0; j < jmax; ++j){
            cpa_wait0();
            __syncthreads();                      // data visible + prev tile consumed

            if (j + 1 < jmax){                    // prefetch next tile into alt buffers
                const char* sK = gK + (size_t)(j+1) * 16384;
                const char* sV = gV + (size_t)(j+1) * 16384;
                uint32_t dK = smb + ((j & 1) ? B_K0 : B_K1);
                uint32_t dV = smb + ((j & 1) ? B_V0 : B_V1);
                #pragma unroll
                for (int it = 0; it < 4; ++it){
                    int i = it*NT + tid; int r = i >> 4, c = (i & 15) * 16;
                    cpa16(dK + r*KSTR + c, sK + r*256 + c);
                }
                #pragma unroll
                for (int it = 0; it < 4; ++it){
                    int i = it*NT + tid; int r = i >> 3, c = (i & 7) * 16;
                    cpa16(dV + r*VSTR + c, sV + r*128 + c);
                }
                cpa_commit();
            }

            if (j * BN <= q0 + mbase + 15){       // warp has unmasked work
                const uint32_t kb_ = smb + ((j & 1) ? B_K1 : B_K0) + kOff;

                // ---- MMA1: S = Q K^T  (16x64, k=128; LDSM.x4 fragments) ----
                float s[8][4];
                #pragma unroll
                for (int nt = 0; nt < 8; ++nt)
                    s[nt][0] = s[nt][1] = s[nt][2] = s[nt][3] = 0.f;
                #pragma unroll
                for (int sb = 0; sb < 4; ++sb){    // 2 k-steps per sb
                    uint4 A0 = ldsm4(qln + sb*64);        // A-frag, k-step 2sb
                    uint4 A1 = ldsm4(qln + sb*64 + 32);   // A-frag, k-step 2sb+1
                    #pragma unroll
                    for (int nt = 0; nt < 8; ++nt){
                        uint4 Bm = ldsm4(kb_ + nt*8*KSTR + sb*64);  // b-frags 2 k-steps
                        mma16816(s[nt], A0.x, A0.y, A0.z, A0.w, Bm.x, Bm.y);
                        mma16816(s[nt], A1.x, A1.y, A1.z, A1.w, Bm.z, Bm.w);
                    }
                }

                // ---- Causal mask (tiles overlapping the diagonal) ----
                if ((j + 1) * BN > q0 + mbase){
                    int r0 = q0 + mbase + gid, r1 = r0 + 8;
                    int cb = j * BN + 2*t4;
                    #pragma unroll
                    for (int nt = 0; nt < 8; ++nt){
                        int c = cb + nt*8;
                        if (c     > r0) s[nt][0] = NEGINF;
                        if (c + 1 > r0) s[nt][1] = NEGINF;
                        if (c     > r1) s[nt][2] = NEGINF;
                        if (c + 1 > r1) s[nt][3] = NEGINF;
                    }
                }

                // ---- Warp-local online softmax ----
                float mx0 = NEGINF, mx1 = NEGINF;
                #pragma unroll
                for (int nt = 0; nt < 8; ++nt){
                    mx0 = fmaxf(mx0, fmaxf(s[nt][0], s[nt][1]));
                    mx1 = fmaxf(mx1, fmaxf(s[nt][2], s[nt][3]));
                }
                mx0 = fmaxf(mx0, __shfl_xor_sync(0xffffffffu, mx0, 1));
                mx0 = fmaxf(mx0, __shfl_xor_sync(0xffffffffu, mx0, 2));
                mx1 = fmaxf(mx1, __shfl_xor_sync(0xffffffffu, mx1, 1));
                mx1 = fmaxf(mx1, __shfl_xor_sync(0xffffffffu, mx1, 2));
                float n0 = fmaxf(m0, mx0), n1 = fmaxf(m1, mx1);
                float al0 = ex2f(m0 - n0), al1 = ex2f(m1 - n1);
                m0 = n0; m1 = n1;

                uint32_t P[16];
                float rs0 = 0.f, rs1 = 0.f;
                #pragma unroll
                for (int nt = 0; nt < 8; ++nt){
                    float p0 = ex2f(s[nt][0] - m0), p1 = ex2f(s[nt][1] - m0);
                    float p2 = ex2f(s[nt][2] - m1), p3 = ex2f(s[nt][3] - m1);
                    rs0 += p0 + p1;  rs1 += p2 + p3;
                    int ks = nt >> 1, hh = nt & 1;
                    P[ks*4 + hh*2 + 0] = packh2(p0, p1);   // A-frag rows gid
                    P[ks*4 + hh*2 + 1] = packh2(p2, p3);   // A-frag rows gid+8
                }
                rs0 += __shfl_xor_sync(0xffffffffu, rs0, 1);
                rs0 += __shfl_xor_sync(0xffffffffu, rs0, 2);
                rs1 += __shfl_xor_sync(0xffffffffu, rs1, 1);
                rs1 += __shfl_xor_sync(0xffffffffu, rs1, 2);
                l0 = l0*al0 + rs0;
                l1 = l1*al1 + rs1;

                // Rescale O only when some row max actually moved
                if (__any_sync(0xffffffffu, (al0 != 1.f) | (al1 != 1.f))){
                    #pragma unroll
                    for (int nt = 0; nt < 16; ++nt){
                        o[nt][0] *= al0; o[nt][1] *= al0;
                        o[nt][2] *= al1; o[nt][3] *= al1;
                    }
                }

                // ---- MMA2: O += P V  (P in regs, k=64; LDSM.x4 V fragments) ----
                const uint32_t vb_ = smb + ((j & 1) ? B_V1 : B_V0) + vOff;
                #pragma unroll
                for (int ksb = 0; ksb < 2; ++ksb){   // 2 k-steps per ksb
                    uint32_t a0 = P[8*ksb+0], a1 = P[8*ksb+1], a2 = P[8*ksb+2], a3 = P[8*ksb+3];
                    uint32_t b0 = P[8*ksb+4], b1 = P[8*ksb+5], b2 = P[8*ksb+6], b3 = P[8*ksb+7];
                    #pragma unroll
                    for (int nt = 0; nt < 16; ++nt){
                        uint4 Bm = ldsm4(vb_ + nt*8*VSTR + ksb*64);
                        mma16816(o[nt], a0, a1, a2, a3, Bm.x, Bm.y);
                        mma16816(o[nt], b0, b1, b2, b3, Bm.z, Bm.w);
                    }
                }
            }
        }

        // ---- Epilogue: O / l -> Out[(q0+row), head*128 + d] ----
        float i0 = 1.0f / l0, i1 = 1.0f / l1;
        float* po = Out + (size_t)(q0 + mbase + gid) * DM + head * DH + 2*t4;
        #pragma unroll
        for (int nt = 0; nt < 16; ++nt){
            *(float2*)(po + nt*8)        = make_float2(o[nt][0]*i0, o[nt][1]*i0);
            *(float2*)(po + 8*DM + nt*8) = make_float2(o[nt][2]*i1, o[nt][3]*i1);
        }
    }
}

extern "C" void kernel_launch(void* const* d_in, const int* in_sizes, int n_in,
                              void* d_out, int out_size)
{
    (void)in_sizes; (void)n_in; (void)out_size;
    const float* q = (const float*)d_in[0];
    const float* k = (const float*)d_in[1];
    const float* v = (const float*)d_in[2];
    float* out = (float*)d_out;

    prep_all<<<4096, 256>>>(q, k, v);

    cudaFuncSetAttribute(fa_kernel,
                         cudaFuncAttributeMaxDynamicSharedMemorySize, SMEM_BYTES);
    fa_kernel<<<296, NT, SMEM_BYTES>>>(out);
}

// round 14
// speedup vs baseline: 1.1016x; 1.1016x over previous
#include <cuda_runtime.h>
#include <cuda_fp16.h>
#include <cstdint>

#define H  16
#define S  4096
#define DH 128
#define DM 2048
#define BM 128
#define BN 64
#define NT 256            // 8 warps, each owns 16 Q rows x full KV width
#define NQT 32            // S/BM Q-tiles per head

// byte offsets in dynamic SMEM
#define QSTR  288         // bytes per Q row (128 halfs + 16 pad)
#define KSTR  288
#define VSTR  160         // V row: 64 halfs + pad
#define B_Q   0
#define KSZ   (64*KSTR)   // 18432
#define VSZ   (128*VSTR)  // 20480
#define B_K0  (128*QSTR)          // 36864
#define B_K1  (B_K0 + KSZ)
#define B_V0  (B_K1 + KSZ)
#define B_V1  (B_V0 + VSZ)
#define SMEM_BYTES (B_V1 + VSZ)   // 114688 -> 2 CTAs/SM

// Prepass scratch: fp16, pair-permuted (LDS.64 fragment loads).
// g_Qh/g_Kh: [head][row][d(128)] (Q pre-scaled). g_Vh: [head][kvTile(64)][d(128)][kv(64)]
__device__ __align__(16) __half g_Qh[H*S*DH];
__device__ __align__(16) __half g_Kh[H*S*DH];
__device__ __align__(16) __half g_Vh[H*S*DH];

__device__ __forceinline__ float ex2f(float x){
    float r; asm("ex2.approx.ftz.f32 %0, %1;" : "=f"(r) : "f"(x)); return r;
}
__device__ __forceinline__ uint32_t packh2(float lo, float hi){
    uint32_t d; asm("cvt.rn.f16x2.f32 %0, %1, %2;" : "=r"(d) : "f"(hi), "f"(lo));
    return d;
}
__device__ __forceinline__ uint32_t h2ex2(uint32_t x){
    uint32_t r; asm("ex2.approx.f16x2 %0, %1;" : "=r"(r) : "r"(x)); return r;
}
__device__ __forceinline__ void mma16816(float c[4],
    uint32_t a0, uint32_t a1, uint32_t a2, uint32_t a3, uint32_t b0, uint32_t b1)
{
    asm volatile(
        "mma.sync.aligned.m16n8k16.row.col.f32.f16.f16.f32 "
        "{%0,%1,%2,%3}, {%4,%5,%6,%7}, {%8,%9}, {%0,%1,%2,%3};\n"
        : "+f"(c[0]), "+f"(c[1]), "+f"(c[2]), "+f"(c[3])
        : "r"(a0), "r"(a1), "r"(a2), "r"(a3), "r"(b0), "r"(b1));
}
__device__ __forceinline__ void cpa16(uint32_t dst, const void* src){
    asm volatile("cp.async.cg.shared.global [%0], [%1], 16;" :: "r"(dst), "l"(src));
}
__device__ __forceinline__ void cpa_commit(){
    asm volatile("cp.async.commit_group;" ::: "memory");
}
__device__ __forceinline__ void cpa_wait0(){
    asm volatile("cp.async.wait_group 0;" ::: "memory");
}

// ---- Fused prepass: blocks [0,2048) convert Q,K; blocks [2048,4096) convert V ----
__global__ void prep_all(const float* __restrict__ Q, const float* __restrict__ K,
                         const float* __restrict__ V)
{
    if (blockIdx.x < 2048){
        const float SC = 0.088388347648318447f * 1.4426950408889634f; // 1/sqrt(128)*log2e
        size_t base = ((size_t)blockIdx.x * 256 + threadIdx.x) * 16;
        {
            const float4* q = (const float4*)(Q + base);
            float4 x0=q[0], x1=q[1], x2=q[2], x3=q[3];
            __half2 h[8];
            h[0]=__floats2half2_rn(x0.x*SC,x0.y*SC); h[1]=__floats2half2_rn(x2.x*SC,x2.y*SC);
            h[2]=__floats2half2_rn(x0.z*SC,x0.w*SC); h[3]=__floats2half2_rn(x2.z*SC,x2.w*SC);
            h[4]=__floats2half2_rn(x1.x*SC,x1.y*SC); h[5]=__floats2half2_rn(x3.x*SC,x3.y*SC);
            h[6]=__floats2half2_rn(x1.z*SC,x1.w*SC); h[7]=__floats2half2_rn(x3.z*SC,x3.w*SC);
            *(float4*)(g_Qh+base)   = *(float4*)(h);
            *(float4*)(g_Qh+base+8) = *(float4*)(h+4);
        }
        {
            const float4* k = (const float4*)(K + base);
            float4 x0=k[0], x1=k[1], x2=k[2], x3=k[3];
            __half2 h[8];
            h[0]=__floats2half2_rn(x0.x,x0.y); h[1]=__floats2half2_rn(x2.x,x2.y);
            h[2]=__floats2half2_rn(x0.z,x0.w); h[3]=__floats2half2_rn(x2.z,x2.w);
            h[4]=__floats2half2_rn(x1.x,x1.y); h[5]=__floats2half2_rn(x3.x,x3.y);
            h[6]=__floats2half2_rn(x1.z,x1.w); h[7]=__floats2half2_rn(x3.z,x3.w);
            *(float4*)(g_Kh+base)   = *(float4*)(h);
            *(float4*)(g_Kh+base+8) = *(float4*)(h+4);
        }
    } else {
        int b2   = blockIdx.x - 2048;           // [0,2048)
        int head = b2 >> 7;
        int T    = (b2 >> 1) & 63;
        int kb   = (b2 & 1) * 2 + (threadIdx.x >> 7);
        int d    = threadIdx.x & 127;
        int kv0  = T * 64 + kb * 16;
        const float* src = V + ((size_t)head * S + kv0) * DH + d;
        float x[16];
        #pragma unroll
        for (int w = 0; w < 16; ++w) x[w] = src[(size_t)w * DH];
        __half2 h[8];
        h[0]=__floats2half2_rn(x[0],x[1]);   h[1]=__floats2half2_rn(x[8],x[9]);
        h[2]=__floats2half2_rn(x[2],x[3]);   h[3]=__floats2half2_rn(x[10],x[11]);
        h[4]=__floats2half2_rn(x[4],x[5]);   h[5]=__floats2half2_rn(x[12],x[13]);
        h[6]=__floats2half2_rn(x[6],x[7]);   h[7]=__floats2half2_rn(x[14],x[15]);
        __half* dst = g_Vh + (((size_t)head*64 + T)*128 + d)*64 + kb*16;
        *(float4*)(dst)   = *(float4*)(h);
        *(float4*)(dst+8) = *(float4*)(h+4);
    }
}

// ---------------- Main flash-attention kernel ----------------
// 296-CTA static schedule (2 CTAs/SM exactly; per-CTA cost in [28,32] units):
//   bid <  80 : single tile  head=bid&15,  qt=31-(bid>>4)
//   bid >= 80 : p2=bid-80
//     p2 < 208: same-head pair  head=p2&15, tiles qt=26-(p2>>4), qt=(p2>>4)
//     else    : cross-head pair i=p2-208: (head=2i,qt=13),(head=2i+1,qt=13)
extern __shared__ char smc[];

__global__ __launch_bounds__(NT, 2)
void fa_kernel(float* __restrict__ Out)
{
    const int bid = (int)blockIdx.x;
    int h0, q0t, h1, q1t, nseg;
    if (bid < 80){
        h0 = bid & 15;  q0t = 31 - (bid >> 4);
        h1 = 0; q1t = 0; nseg = 1;
    } else {
        int p2 = bid - 80;
        if (p2 < 208){
            int c = p2 >> 4;
            h0 = h1 = p2 & 15;
            q0t = 26 - c;  q1t = c;
        } else {
            int i = p2 - 208;
            h0 = 2*i;  h1 = 2*i + 1;
            q0t = q1t = 13;
        }
        nseg = 2;
    }

    const int tid  = threadIdx.x;
    const int lane = tid & 31;
    const int warp = tid >> 5;
    const int gid  = lane >> 2;
    const int t4   = lane & 3;
    const int mbase = warp * 16;       // this warp's 16 rows

    const uint32_t smb = (uint32_t)__cvta_generic_to_shared(smc);
    const float NEGINF = __int_as_float(0xff800000);
    const uint32_t ONE2 = 0x3C003C00u;   // (1.0h, 1.0h): B-frag of an all-ones column

    #pragma unroll 1
    for (int seg = 0; seg < nseg; ++seg){
        const int head = seg ? h1 : h0;
        const int qt   = seg ? q1t : q0t;
        const int q0   = qt * BM;
        const int jmax = 2*qt + 2;
        const char* gQ = (const char*)(g_Qh + ((size_t)head*S + q0) * DH);
        const char* gK = (const char*)(g_Kh + (size_t)head*S*DH);
        const char* gV = (const char*)(g_Vh + (size_t)head*S*DH);

        __syncthreads();   // prior segment fully done with all SMEM buffers

        // ---- Prologue: Q tile + K/V tile 0 ----
        #pragma unroll
        for (int it = 0; it < 8; ++it){
            int i = it*NT + tid; int r = i >> 4, c = (i & 15) * 16;
            cpa16(smb + B_Q + r*QSTR + c, gQ + r*256 + c);
        }
        #pragma unroll
        for (int it = 0; it < 4; ++it){
            int i = it*NT + tid; int r = i >> 4, c = (i & 15) * 16;
            cpa16(smb + B_K0 + r*KSTR + c, gK + r*256 + c);
        }
        #pragma unroll
        for (int it = 0; it < 4; ++it){
            int i = it*NT + tid; int r = i >> 3, c = (i & 7) * 16;
            cpa16(smb + B_V0 + r*VSTR + c, gV + r*128 + c);
        }
        cpa_commit();

        float o[16][4];
        #pragma unroll
        for (int nt = 0; nt < 16; ++nt)
            o[nt][0] = o[nt][1] = o[nt][2] = o[nt][3] = 0.f;
        float ox[4] = {0.f, 0.f, 0.f, 0.f};  // ones-column accum: l in ox[0]/ox[2]
        float m0 = NEGINF, m1 = NEGINF;

        #pragma unroll 1
        for (int j = 0; j < jmax; ++j){
            cpa_wait0();
            __syncthreads();                      // data visible + prev tile consumed

            if (j + 1 < jmax){                    // prefetch next tile into alt buffers
                const char* sK = gK + (size_t)(j+1) * 16384;
                const char* sV = gV + (size_t)(j+1) * 16384;
                uint32_t dK = smb + ((j & 1) ? B_K0 : B_K1);
                uint32_t dV = smb + ((j & 1) ? B_V0 : B_V1);
                #pragma unroll
                for (int it = 0; it < 4; ++it){
                    int i = it*NT + tid; int r = i >> 4, c = (i & 15) * 16;
                    cpa16(dK + r*KSTR + c, sK + r*256 + c);
                }
                #pragma unroll
                for (int it = 0; it < 4; ++it){
                    int i = it*NT + tid; int r = i >> 3, c = (i & 7) * 16;
                    cpa16(dV + r*VSTR + c, sV + r*128 + c);
                }
                cpa_commit();
            }

            if (j * BN <= q0 + mbase + 15){       // warp has unmasked work
                const char* qp = smc + B_Q + (mbase + gid)*QSTR + t4*8;
                const char* kp = smc + ((j & 1) ? B_K1 : B_K0) + gid*KSTR + t4*8;

                // ---- MMA1: S = Q K^T  (16 rows x 64 cols, k=128) ----
                float s[8][4];
                #pragma unroll
                for (int nt = 0; nt < 8; ++nt)
                    s[nt][0] = s[nt][1] = s[nt][2] = s[nt][3] = 0.f;
                #pragma unroll
                for (int ks = 0; ks < 8; ++ks){
                    uint2 A02 = *(const uint2*)(qp + ks*32);
                    uint2 A13 = *(const uint2*)(qp + 8*QSTR + ks*32);
                    #pragma unroll
                    for (int nt = 0; nt < 8; ++nt){
                        uint2 B = *(const uint2*)(kp + nt*8*KSTR + ks*32);
                        mma16816(s[nt], A02.x, A13.x, A02.y, A13.y, B.x, B.y);
                    }
                }

                // ---- Causal mask (tiles overlapping the diagonal) ----
                if ((j + 1) * BN > q0 + mbase){
                    int r0 = q0 + mbase + gid, r1 = r0 + 8;
                    int cb = j * BN + 2*t4;
                    #pragma unroll
                    for (int nt = 0; nt < 8; ++nt){
                        int c = cb + nt*8;
                        if (c     > r0) s[nt][0] = NEGINF;
                        if (c + 1 > r0) s[nt][1] = NEGINF;
                        if (c     > r1) s[nt][2] = NEGINF;
                        if (c + 1 > r1) s[nt][3] = NEGINF;
                    }
                }

                // ---- Warp-local online softmax (max only; sum rides in MMA2) ----
                float mx0 = NEGINF, mx1 = NEGINF;
                #pragma unroll
                for (int nt = 0; nt < 8; ++nt){
                    mx0 = fmaxf(mx0, fmaxf(s[nt][0], s[nt][1]));
                    mx1 = fmaxf(mx1, fmaxf(s[nt][2], s[nt][3]));
                }
                mx0 = fmaxf(mx0, __shfl_xor_sync(0xffffffffu, mx0, 1));
                mx0 = fmaxf(mx0, __shfl_xor_sync(0xffffffffu, mx0, 2));
                mx1 = fmaxf(mx1, __shfl_xor_sync(0xffffffffu, mx1, 1));
                mx1 = fmaxf(mx1, __shfl_xor_sync(0xffffffffu, mx1, 2));
                float n0 = fmaxf(m0, mx0), n1 = fmaxf(m1, mx1);
                float al0 = ex2f(m0 - n0), al1 = ex2f(m1 - n1);
                m0 = n0; m1 = n1;

                // P = ex2(s - m) computed in f16x2 (P feeds the MMA as fp16 anyway)
                uint32_t P[16];
                #pragma unroll
                for (int nt = 0; nt < 8; ++nt){
                    uint32_t elo = packh2(s[nt][0] - m0, s[nt][1] - m0);
                    uint32_t ehi = packh2(s[nt][2] - m1, s[nt][3] - m1);
                    int ks = nt >> 1, hh = nt & 1;
                    P[ks*4 + hh*2 + 0] = h2ex2(elo);   // A-frag rows gid
                    P[ks*4 + hh*2 + 1] = h2ex2(ehi);   // A-frag rows gid+8
                }

                // Rescale O (and the l accumulator) only when a row max moved
                if (__any_sync(0xffffffffu, (al0 != 1.f) | (al1 != 1.f))){
                    #pragma unroll
                    for (int nt = 0; nt < 16; ++nt){
                        o[nt][0] *= al0; o[nt][1] *= al0;
                        o[nt][2] *= al1; o[nt][3] *= al1;
                    }
                    ox[0] *= al0; ox[1] *= al0; ox[2] *= al1; ox[3] *= al1;
                }

                // ---- MMA2: [O | l] += P [V | 1]  (ones column = constant B-frag) ----
                const char* vp = smc + ((j & 1) ? B_V1 : B_V0) + gid*VSTR + t4*8;
                #pragma unroll
                for (int ks = 0; ks < 4; ++ks){
                    uint32_t a0 = P[ks*4], a1 = P[ks*4+1], a2 = P[ks*4+2], a3 = P[ks*4+3];
                    #pragma unroll
                    for (int nt = 0; nt < 16; ++nt){
                        uint2 B = *(const uint2*)(vp + nt*8*VSTR + ks*32);
                        mma16816(o[nt], a0, a1, a2, a3, B.x, B.y);
                    }
                    mma16816(ox, a0, a1, a2, a3, ONE2, ONE2);
                }
            }
        }

        // ---- Epilogue: l = ox (all accumulator columns equal; no shuffle) ----
        float i0 = 1.0f / ox[0], i1 = 1.0f / ox[2];
        float* po = Out + (size_t)(q0 + mbase + gid) * DM + head * DH + 2*t4;
        #pragma unroll
        for (int nt = 0; nt < 16; ++nt){
            *(float2*)(po + nt*8)        = make_float2(o[nt][0]*i0, o[nt][1]*i0);
            *(float2*)(po + 8*DM + nt*8) = make_float2(o[nt][2]*i1, o[nt][3]*i1);
        }
    }
}

extern "C" void kernel_launch(void* const* d_in, const int* in_sizes, int n_in,
                              void* d_out, int out_size)
{
    (void)in_sizes; (void)n_in; (void)out_size;
    const float* q = (const float*)d_in[0];
    const float* k = (const float*)d_in[1];
    const float* v = (const float*)d_in[2];
    float* out = (float*)d_out;

    prep_all<<<4096, 256>>>(q, k, v);

    cudaFuncSetAttribute(fa_kernel,
                         cudaFuncAttributeMaxDynamicSharedMemorySize, SMEM_BYTES);
    fa_kernel<<<296, NT, SMEM_BYTES>>>(out);
}